// round 10
// baseline (speedup 1.0000x reference)
#include <cuda_runtime.h>

#define T_LEN   16384
#define NUMB    64
#define KTAPS   129
#define TILE_T  128
#define TPB     2       // tiles per block
#define BPB     8       // bands per block (1 per warp)
#define THREADS 256
#define NGROUPS (NUMB / BPB)
#define NTILES  (T_LEN / TILE_T)

// t-major partials: 8 floats (=2x float4) per t, one slot per band group
__device__ float4 g_part[T_LEN][2];
// per-tile arrival tickets; zero-init at load, reset by finalizer each launch
__device__ int g_cnt[NTILES];

__device__ __forceinline__ float ex2f(float x) {
    float r; asm("ex2.approx.ftz.f32 %0, %1;" : "=f"(r) : "f"(x)); return r;
}
__device__ __forceinline__ float sqrtaf(float x) {
    float r; asm("sqrt.approx.f32 %0, %1;" : "=f"(r) : "f"(x)); return r;
}

__global__ __launch_bounds__(THREADS, 5)
void fused_kernel(const float* __restrict__ xr, const float* __restrict__ xi,
                  const float* __restrict__ w1r, const float* __restrict__ w1i,
                  const float* __restrict__ cr,  const float* __restrict__ ci,
                  const float* __restrict__ sr,  const float* __restrict__ si,
                  const float* __restrict__ fr,  const float* __restrict__ fi,
                  const float* __restrict__ w3r, const float* __restrict__ w3i,
                  float* __restrict__ out)
{
    // conv x-arrays and sred never live simultaneously -> union (sync-guarded)
    __shared__ __align__(16) union {
        struct { float r[TILE_T + 128]; float i[TILE_T + 128]; float s[TILE_T + 128]; } cx;
        float sred[BPB][TILE_T];
    } u;
    __shared__ __align__(16) float swr[BPB][132];   // wr
    __shared__ __align__(16) float swd[BPB][132];   // wi - wr
    __shared__ __align__(16) float sws[BPB][132];   // wi + wr
    __shared__ __align__(16) float4 sPq[BPB][NUMB]; // {pxr, pyr, pxi, pyi}
    __shared__ __align__(16) float2 sPw[BPB][NUMB]; // {fc_r*2^pzr, fc_i*2^pzi}
    __shared__ int s_ticket;

    const int tid  = threadIdx.x;
    const int wb   = tid >> 5;        // local band (warp)
    const int lane = tid & 31;
    const int band = blockIdx.y * BPB + wb;

    // ---- stage Karatsuba weight triplets (once, reused for TPB tiles) ----
    for (int i = tid; i < BPB * KTAPS; i += THREADS) {
        int bb = i / KTAPS, k = i - bb * KTAPS;
        int gb = blockIdx.y * BPB + bb;
        float wr = w1r[gb * KTAPS + k];
        float wi = w1i[gb * KTAPS + k];
        swr[bb][k] = wr;
        swd[bb][k] = wi - wr;
        sws[bb][k] = wi + wr;
    }
    // ---- inline RBF param precompute (2^pz folded into mixture weight) ----
    const float L = 1.4426950408889634f;  // log2(e)
    for (int i = tid; i < BPB * NUMB; i += THREADS) {
        int bb = i >> 6, c = i & 63;
        int idx = (blockIdx.y * BPB + bb) * NUMB + c;
        float s  = __ldg(&sr[idx]) * L;
        float cc = __ldg(&cr[idx]);
        float pxr = -s, pyr = 2.0f * s * cc;
        float pwr = __ldg(&fr[idx]) * ex2f(-s * cc * cc);
        s  = __ldg(&si[idx]) * L;
        cc = __ldg(&ci[idx]);
        float pxi = -s, pyi = 2.0f * s * cc;
        float pwi = __ldg(&fi[idx]) * ex2f(-s * cc * cc);
        sPq[bb][c] = make_float4(pxr, pyr, pxi, pyi);
        sPw[bb][c] = make_float2(pwr, pwi);
    }

    const float w3rb = __ldg(&w3r[band]);
    const float w3ib = __ldg(&w3i[band]);

    for (int it = 0; it < TPB; it++) {
        const int tile = blockIdx.x * TPB + it;
        const int tileBase = tile * TILE_T;

        // protect union (prev iteration's sred readers) before restaging x
        __syncthreads();
        for (int i = tid; i < TILE_T + 128; i += THREADS) {
            int t = tileBase - 64 + i;
            bool ok = (t >= 0) && (t < T_LEN);
            float vr = ok ? xr[t] : 0.0f;
            float vi = ok ? xi[t] : 0.0f;
            u.cx.r[i] = vr;
            u.cx.i[i] = vi;
            u.cx.s[i] = vr + vi;
        }
        __syncthreads();

        // ---- Karatsuba complex conv: 3 FFMA/tap/output ----
        // A = sum wr*(xr+xi), B = sum xr*(wi-wr), C = sum xi*(wi+wr)
        // x1r = A - C, x1i = A + B
        float A[4] = {0.f,0.f,0.f,0.f}, B[4] = {0.f,0.f,0.f,0.f}, C[4] = {0.f,0.f,0.f,0.f};
        const float4* xs4 = (const float4*)u.cx.s;
        const float4* xr4 = (const float4*)u.cx.r;
        const float4* xi4 = (const float4*)u.cx.i;

        float4 As = xs4[lane], Ar = xr4[lane], Ai = xi4[lane];
        #pragma unroll
        for (int kg = 0; kg < 32; kg++) {
            float4 Bs = xs4[lane + kg + 1];
            float4 Br = xr4[lane + kg + 1];
            float4 Bi = xi4[lane + kg + 1];
            float4 wr4 = *(const float4*)&swr[wb][4 * kg];
            float4 wd4 = *(const float4*)&swd[wb][4 * kg];
            float4 ws4 = *(const float4*)&sws[wb][4 * kg];
            float axs[8] = {As.x, As.y, As.z, As.w, Bs.x, Bs.y, Bs.z, Bs.w};
            float axr[8] = {Ar.x, Ar.y, Ar.z, Ar.w, Br.x, Br.y, Br.z, Br.w};
            float axi[8] = {Ai.x, Ai.y, Ai.z, Ai.w, Bi.x, Bi.y, Bi.z, Bi.w};
            float wrv[4] = {wr4.x, wr4.y, wr4.z, wr4.w};
            float wdv[4] = {wd4.x, wd4.y, wd4.z, wd4.w};
            float wsv[4] = {ws4.x, ws4.y, ws4.z, ws4.w};
            #pragma unroll
            for (int kk = 0; kk < 4; kk++) {
                #pragma unroll
                for (int j = 0; j < 4; j++) {
                    A[j] = fmaf(axs[kk + j], wrv[kk], A[j]);
                    B[j] = fmaf(axr[kk + j], wdv[kk], B[j]);
                    C[j] = fmaf(axi[kk + j], wsv[kk], C[j]);
                }
            }
            As = Bs; Ar = Br; Ai = Bi;
        }
        {   // tail tap k = 128: window float4 already in As/Ar/Ai
            float wr = swr[wb][128], wd = swd[wb][128], ws = sws[wb][128];
            float ts[4] = {As.x, As.y, As.z, As.w};
            float tr[4] = {Ar.x, Ar.y, Ar.z, Ar.w};
            float ti[4] = {Ai.x, Ai.y, Ai.z, Ai.w};
            #pragma unroll
            for (int j = 0; j < 4; j++) {
                A[j] = fmaf(ts[j], wr, A[j]);
                B[j] = fmaf(tr[j], wd, B[j]);
                C[j] = fmaf(ti[j], ws, C[j]);
            }
        }
        float x1r[4], x1i[4];
        #pragma unroll
        for (int j = 0; j < 4; j++) {
            x1r[j] = A[j] - C[j];
            x1i[j] = A[j] + B[j];
        }

        // ---- RBF mixture: exp2(m*px + a*py) * pw' ----
        float m[4], a[4], oR[4] = {0.f,0.f,0.f,0.f}, oI[4] = {0.f,0.f,0.f,0.f};
        #pragma unroll
        for (int j = 0; j < 4; j++) {
            m[j] = x1r[j] * x1r[j] + x1i[j] * x1i[j];
            a[j] = sqrtaf(m[j]);
        }
        #pragma unroll 4
        for (int c = 0; c < NUMB; c++) {
            float4 q = sPq[wb][c];
            float2 w = sPw[wb][c];
            #pragma unroll
            for (int j = 0; j < 4; j++) {
                float er = ex2f(fmaf(m[j], q.x, a[j] * q.y));
                oR[j] = fmaf(er, w.x, oR[j]);
                float ei = ex2f(fmaf(m[j], q.z, a[j] * q.w));
                oI[j] = fmaf(ei, w.y, oI[j]);
            }
        }

        // ---- combine + band weight (real output only) ----
        float yv[4];
        #pragma unroll
        for (int j = 0; j < 4; j++) {
            float q   = oR[j] + 1.0f;
            float x2r = q * x1r[j] - oI[j] * x1i[j];
            float x2i = q * x1i[j] + oI[j] * x1r[j];
            yv[j] = x2r * w3rb - x2i * w3ib;   // real part of y3
        }
        __syncthreads();   // all warps done reading u.cx before overlay reuse
        #pragma unroll
        for (int j = 0; j < 4; j++)
            u.sred[wb][4 * lane + j] = yv[j];
        __syncthreads();

        // ---- reduce 8 bands within block; publish t-major partial ----
        if (tid < TILE_T) {
            float r = 0.f;
            #pragma unroll
            for (int w = 0; w < BPB; w++) r += u.sred[w][tid];
            ((float*)&g_part[tileBase + tid][0])[blockIdx.y] = r;
        }

        // ---- fence + ticket: last block of this tile finalizes ----
        __threadfence();
        if (tid == 0)
            s_ticket = atomicAdd(&g_cnt[tile], 1);
        __syncthreads();
        if (s_ticket == NGROUPS - 1) {
            if (tid < TILE_T) {
                int t = tileBase + tid;
                float4 pa = g_part[t][0];
                float4 pb = g_part[t][1];
                out[t] = ((pa.x + pa.y) + (pa.z + pa.w)) + ((pb.x + pb.y) + (pb.z + pb.w));
            }
            if (tid == 0)
                g_cnt[tile] = 0;   // reset for next launch / graph replay
        }
    }
}

extern "C" void kernel_launch(void* const* d_in, const int* in_sizes, int n_in,
                              void* d_out, int out_size)
{
    // Input ordering: order A (dict/signature) confirmed (in_sizes[0]==16384).
    int I_xr, I_xi, I_w1r, I_w1i, I_cr, I_ci, I_sr, I_si, I_fcr, I_fci, I_w3r, I_w3i;
    if (in_sizes[0] == T_LEN) {
        I_xr = 0;  I_xi = 1;  I_w1r = 2; I_w1i = 3; I_cr = 4;  I_ci = 5;
        I_sr = 6;  I_si = 7;  I_fcr = 8; I_fci = 9; I_w3r = 10; I_w3i = 11;
    } else {
        I_ci = 0;  I_cr = 1;  I_fci = 2; I_fcr = 3; I_si = 4;  I_sr = 5;
        I_w1i = 6; I_w1r = 7; I_w3i = 8; I_w3r = 9; I_xi = 10; I_xr = 11;
    }

    const float* x_r  = (const float*)d_in[I_xr];
    const float* x_i  = (const float*)d_in[I_xi];
    const float* w1_r = (const float*)d_in[I_w1r];
    const float* w1_i = (const float*)d_in[I_w1i];
    const float* c_r  = (const float*)d_in[I_cr];
    const float* c_i  = (const float*)d_in[I_ci];
    const float* s_r  = (const float*)d_in[I_sr];
    const float* s_i  = (const float*)d_in[I_si];
    const float* fc_r = (const float*)d_in[I_fcr];
    const float* fc_i = (const float*)d_in[I_fci];
    const float* w3_r = (const float*)d_in[I_w3r];
    const float* w3_i = (const float*)d_in[I_w3i];
    float* out = (float*)d_out;

    dim3 grid(NTILES / TPB, NGROUPS);
    fused_kernel<<<grid, THREADS>>>(x_r, x_i, w1_r, w1_i,
                                    c_r, c_i, s_r, s_i, fc_r, fc_i,
                                    w3_r, w3_i, out);
}

// round 11
// speedup vs baseline: 1.1909x; 1.1909x over previous
#include <cuda_runtime.h>

#define T_LEN   16384
#define NUMB    64
#define KTAPS   129
#define TILE_T  128
#define BPB     8       // bands per block (1 per warp)
#define THREADS 256
#define NGROUPS (NUMB / BPB)
#define NTILES  (T_LEN / TILE_T)

// t-major partials: 8 floats (=2x float4) per t, one slot per band group
__device__ float4 g_part[T_LEN][2];
// per-tile arrival tickets; zero-init at load, reset by finalizer each launch
__device__ int g_cnt[NTILES];

__device__ __forceinline__ float ex2f(float x) {
    float r; asm("ex2.approx.ftz.f32 %0, %1;" : "=f"(r) : "f"(x)); return r;
}
__device__ __forceinline__ float sqrtaf(float x) {
    float r; asm("sqrt.approx.f32 %0, %1;" : "=f"(r) : "f"(x)); return r;
}

__global__ __launch_bounds__(THREADS, 5)
void fused_kernel(const float* __restrict__ xr, const float* __restrict__ xi,
                  const float* __restrict__ w1r, const float* __restrict__ w1i,
                  const float* __restrict__ cr,  const float* __restrict__ ci,
                  const float* __restrict__ sr,  const float* __restrict__ si,
                  const float* __restrict__ fr,  const float* __restrict__ fi,
                  const float* __restrict__ w3r, const float* __restrict__ w3i,
                  float* __restrict__ out)
{
    // conv x-arrays and sred never live simultaneously -> union (sync-guarded)
    __shared__ __align__(16) union {
        struct { float r[TILE_T + 128]; float i[TILE_T + 128]; float s[TILE_T + 128]; } cx;
        float sred[BPB][TILE_T];
    } u;
    __shared__ __align__(16) float swr[BPB][132];   // wr
    __shared__ __align__(16) float swd[BPB][132];   // wi - wr
    __shared__ __align__(16) float sws[BPB][132];   // wi + wr
    __shared__ __align__(16) float4 sPq[BPB][NUMB]; // {pxr, pyr, pxi, pyi}
    __shared__ __align__(16) float2 sPw[BPB][NUMB]; // {fc_r*2^pzr, fc_i*2^pzi}
    __shared__ int s_ticket;

    const int tid  = threadIdx.x;
    const int wb   = tid >> 5;        // local band (warp)
    const int lane = tid & 31;
    const int tile = blockIdx.x;
    const int tileBase = tile * TILE_T;
    const int band = blockIdx.y * BPB + wb;

    // ---- stage x tile + halo, with precomputed sum array ----
    for (int i = tid; i < TILE_T + 128; i += THREADS) {
        int t = tileBase - 64 + i;
        bool ok = (t >= 0) && (t < T_LEN);
        float vr = ok ? xr[t] : 0.0f;
        float vi = ok ? xi[t] : 0.0f;
        u.cx.r[i] = vr;
        u.cx.i[i] = vi;
        u.cx.s[i] = vr + vi;
    }
    // ---- stage Karatsuba weight triplets ----
    for (int i = tid; i < BPB * KTAPS; i += THREADS) {
        int bb = i / KTAPS, k = i - bb * KTAPS;
        int gb = blockIdx.y * BPB + bb;
        float wr = w1r[gb * KTAPS + k];
        float wi = w1i[gb * KTAPS + k];
        swr[bb][k] = wr;
        swd[bb][k] = wi - wr;
        sws[bb][k] = wi + wr;
    }
    // ---- inline RBF param precompute (2^pz folded into mixture weight) ----
    const float L = 1.4426950408889634f;  // log2(e)
    for (int i = tid; i < BPB * NUMB; i += THREADS) {
        int bb = i >> 6, c = i & 63;
        int idx = (blockIdx.y * BPB + bb) * NUMB + c;
        float s  = __ldg(&sr[idx]) * L;
        float cc = __ldg(&cr[idx]);
        float pxr = -s, pyr = 2.0f * s * cc;
        float pwr = __ldg(&fr[idx]) * ex2f(-s * cc * cc);
        s  = __ldg(&si[idx]) * L;
        cc = __ldg(&ci[idx]);
        float pxi = -s, pyi = 2.0f * s * cc;
        float pwi = __ldg(&fi[idx]) * ex2f(-s * cc * cc);
        sPq[bb][c] = make_float4(pxr, pyr, pxi, pyi);
        sPw[bb][c] = make_float2(pwr, pwi);
    }
    __syncthreads();

    // ---- Karatsuba complex conv: 3 FFMA/tap/output ----
    // A = sum wr*(xr+xi), B = sum xr*(wi-wr), C = sum xi*(wi+wr)
    // x1r = A - C, x1i = A + B
    float A[4] = {0.f,0.f,0.f,0.f}, B[4] = {0.f,0.f,0.f,0.f}, C[4] = {0.f,0.f,0.f,0.f};
    const float4* xs4 = (const float4*)u.cx.s;
    const float4* xr4 = (const float4*)u.cx.r;
    const float4* xi4 = (const float4*)u.cx.i;

    float4 As = xs4[lane], Ar = xr4[lane], Ai = xi4[lane];
    #pragma unroll
    for (int kg = 0; kg < 32; kg++) {
        float4 Bs = xs4[lane + kg + 1];
        float4 Br = xr4[lane + kg + 1];
        float4 Bi = xi4[lane + kg + 1];
        float4 wr4 = *(const float4*)&swr[wb][4 * kg];
        float4 wd4 = *(const float4*)&swd[wb][4 * kg];
        float4 ws4 = *(const float4*)&sws[wb][4 * kg];
        float axs[8] = {As.x, As.y, As.z, As.w, Bs.x, Bs.y, Bs.z, Bs.w};
        float axr[8] = {Ar.x, Ar.y, Ar.z, Ar.w, Br.x, Br.y, Br.z, Br.w};
        float axi[8] = {Ai.x, Ai.y, Ai.z, Ai.w, Bi.x, Bi.y, Bi.z, Bi.w};
        float wrv[4] = {wr4.x, wr4.y, wr4.z, wr4.w};
        float wdv[4] = {wd4.x, wd4.y, wd4.z, wd4.w};
        float wsv[4] = {ws4.x, ws4.y, ws4.z, ws4.w};
        #pragma unroll
        for (int kk = 0; kk < 4; kk++) {
            #pragma unroll
            for (int j = 0; j < 4; j++) {
                A[j] = fmaf(axs[kk + j], wrv[kk], A[j]);
                B[j] = fmaf(axr[kk + j], wdv[kk], B[j]);
                C[j] = fmaf(axi[kk + j], wsv[kk], C[j]);
            }
        }
        As = Bs; Ar = Br; Ai = Bi;
    }
    {   // tail tap k = 128: window float4 already in As/Ar/Ai (= index lane+32)
        float wr = swr[wb][128], wd = swd[wb][128], ws = sws[wb][128];
        float ts[4] = {As.x, As.y, As.z, As.w};
        float tr[4] = {Ar.x, Ar.y, Ar.z, Ar.w};
        float ti[4] = {Ai.x, Ai.y, Ai.z, Ai.w};
        #pragma unroll
        for (int j = 0; j < 4; j++) {
            A[j] = fmaf(ts[j], wr, A[j]);
            B[j] = fmaf(tr[j], wd, B[j]);
            C[j] = fmaf(ti[j], ws, C[j]);
        }
    }
    float x1r[4], x1i[4];
    #pragma unroll
    for (int j = 0; j < 4; j++) {
        x1r[j] = A[j] - C[j];
        x1i[j] = A[j] + B[j];
    }

    // ---- RBF mixture: exp2(m*px + a*py) * pw' ----
    float m[4], a[4], oR[4] = {0.f,0.f,0.f,0.f}, oI[4] = {0.f,0.f,0.f,0.f};
    #pragma unroll
    for (int j = 0; j < 4; j++) {
        m[j] = x1r[j] * x1r[j] + x1i[j] * x1i[j];
        a[j] = sqrtaf(m[j]);
    }
    #pragma unroll 4
    for (int c = 0; c < NUMB; c++) {
        float4 q = sPq[wb][c];
        float2 w = sPw[wb][c];
        #pragma unroll
        for (int j = 0; j < 4; j++) {
            float er = ex2f(fmaf(m[j], q.x, a[j] * q.y));
            oR[j] = fmaf(er, w.x, oR[j]);
            float ei = ex2f(fmaf(m[j], q.z, a[j] * q.w));
            oI[j] = fmaf(ei, w.y, oI[j]);
        }
    }

    // ---- combine + band weight (real output only) ----
    float w3rb = __ldg(&w3r[band]);
    float w3ib = __ldg(&w3i[band]);
    float yv[4];
    #pragma unroll
    for (int j = 0; j < 4; j++) {
        float q   = oR[j] + 1.0f;
        float x2r = q * x1r[j] - oI[j] * x1i[j];
        float x2i = q * x1i[j] + oI[j] * x1r[j];
        yv[j] = x2r * w3rb - x2i * w3ib;   // real part of y3
    }
    __syncthreads();   // all warps done reading u.cx before overlay reuse
    #pragma unroll
    for (int j = 0; j < 4; j++)
        u.sred[wb][4 * lane + j] = yv[j];
    __syncthreads();

    // ---- reduce 8 bands within block; publish t-major partial ----
    if (tid < TILE_T) {
        float r = 0.f;
        #pragma unroll
        for (int w = 0; w < BPB; w++) r += u.sred[w][tid];
        ((float*)&g_part[tileBase + tid][0])[blockIdx.y] = r;
    }

    // ---- fence + ticket: last block of this tile finalizes ----
    __threadfence();
    if (tid == 0)
        s_ticket = atomicAdd(&g_cnt[tile], 1);
    __syncthreads();
    if (s_ticket == NGROUPS - 1) {
        if (tid < TILE_T) {
            int t = tileBase + tid;
            float4 pa = g_part[t][0];
            float4 pb = g_part[t][1];
            out[t] = ((pa.x + pa.y) + (pa.z + pa.w)) + ((pb.x + pb.y) + (pb.z + pb.w));
        }
        if (tid == 0)
            g_cnt[tile] = 0;   // reset for next launch / graph replay
    }
}

extern "C" void kernel_launch(void* const* d_in, const int* in_sizes, int n_in,
                              void* d_out, int out_size)
{
    // Input ordering: order A (dict/signature) confirmed (in_sizes[0]==16384).
    int I_xr, I_xi, I_w1r, I_w1i, I_cr, I_ci, I_sr, I_si, I_fcr, I_fci, I_w3r, I_w3i;
    if (in_sizes[0] == T_LEN) {
        I_xr = 0;  I_xi = 1;  I_w1r = 2; I_w1i = 3; I_cr = 4;  I_ci = 5;
        I_sr = 6;  I_si = 7;  I_fcr = 8; I_fci = 9; I_w3r = 10; I_w3i = 11;
    } else {
        I_ci = 0;  I_cr = 1;  I_fci = 2; I_fcr = 3; I_si = 4;  I_sr = 5;
        I_w1i = 6; I_w1r = 7; I_w3i = 8; I_w3r = 9; I_xi = 10; I_xr = 11;
    }

    const float* x_r  = (const float*)d_in[I_xr];
    const float* x_i  = (const float*)d_in[I_xi];
    const float* w1_r = (const float*)d_in[I_w1r];
    const float* w1_i = (const float*)d_in[I_w1i];
    const float* c_r  = (const float*)d_in[I_cr];
    const float* c_i  = (const float*)d_in[I_ci];
    const float* s_r  = (const float*)d_in[I_sr];
    const float* s_i  = (const float*)d_in[I_si];
    const float* fc_r = (const float*)d_in[I_fcr];
    const float* fc_i = (const float*)d_in[I_fci];
    const float* w3_r = (const float*)d_in[I_w3r];
    const float* w3_i = (const float*)d_in[I_w3i];
    float* out = (float*)d_out;

    dim3 grid(NTILES, NGROUPS);
    fused_kernel<<<grid, THREADS>>>(x_r, x_i, w1_r, w1_i,
                                    c_r, c_i, s_r, s_i, fc_r, fc_i,
                                    w3_r, w3_i, out);
}